// round 2
// baseline (speedup 1.0000x reference)
#include <cuda_runtime.h>
#include <math.h>

#define LL 256
#define DD 300
#define SS 16
#define KK 16
#define NNODE 48
#define CC 7
#define FEATD 900
#define NEGV -1000000000.0f

// scratch layout (floats):
// P0:0  P1:76800  Q:153600  K:230400  V:307200  ao:384000
// feat:460800 (256*900)  rnorm:691200  nodes:691456 (256*48*300)
// nscore:4377856  nmask:4390144  h:4402432  end:4479232
__device__ float g_scratch[4479232];

// ---------------- generic multi-row matvec ----------------
// out[r, t] = (relu?)( sum_i X[r*ldx+i]*W[i*N+t] + bias[t] )
template<int ROWS>
__global__ void rowgemm_kernel(const float* __restrict__ X, const float* __restrict__ W,
                               const float* __restrict__ bias, float* __restrict__ out,
                               int M, int Kdim, int N, int ldx, int ldo, int do_relu)
{
    extern __shared__ float xs[]; // ROWS*Kdim
    int row0 = blockIdx.x * ROWS;
    int tid = threadIdx.x;
    for (int idx = tid; idx < ROWS * Kdim; idx += blockDim.x) {
        int r = idx / Kdim, i = idx - r * Kdim;
        int rr = row0 + r;
        xs[idx] = (rr < M) ? X[rr * ldx + i] : 0.f;
    }
    __syncthreads();
    if (tid >= N) return;
    float acc[ROWS];
#pragma unroll
    for (int r = 0; r < ROWS; r++) acc[r] = 0.f;
    for (int i = 0; i < Kdim; i++) {
        float w = W[i * N + tid];
#pragma unroll
        for (int r = 0; r < ROWS; r++) acc[r] += xs[r * Kdim + i] * w;
    }
#pragma unroll
    for (int r = 0; r < ROWS; r++) {
        int rr = row0 + r;
        if (rr < M) {
            float v = acc[r] + (bias ? bias[tid] : 0.f);
            if (do_relu) v = fmaxf(v, 0.f);
            out[rr * ldo + tid] = v;
        }
    }
}

// ---------------- RGCN edge scatter ----------------
// hidden[dst] += comp[r,0]*P0[src] + comp[r,1]*P1[src]   (into feat[:,0:300])
__global__ void edge_kernel(const int* __restrict__ src, const int* __restrict__ dst,
                            const int* __restrict__ etype, const float* __restrict__ comp,
                            const float* __restrict__ P0, const float* __restrict__ P1,
                            float* __restrict__ feat, int E)
{
    int idx = blockIdx.x * blockDim.x + threadIdx.x;
    if (idx >= E * DD) return;
    int e = idx / DD, d = idx - e * DD;
    int s = src[e], t = dst[e], r = etype[e];
    float c0 = comp[r * 2], c1 = comp[r * 2 + 1];
    float v = c0 * P0[s * DD + d] + c1 * P1[s * DD + d];
    atomicAdd(&feat[t * FEATD + d], v);
}

// ---------------- windowed 2-head attention (center query only) ----------------
__global__ void relatt_kernel(const float* __restrict__ Q, const float* __restrict__ Kb,
                              const float* __restrict__ V, float* __restrict__ ao)
{
    int l = blockIdx.x;
    int tid = threadIdx.x;
    int wrp = tid >> 5, lane = tid & 31;
    __shared__ float sc[6];
    __shared__ float alpha[6];
    if (wrp < 6) {
        int h = wrp / 3, w = wrp % 3;
        int nl = l + w - 1; nl = max(0, min(LL - 1, nl));
        float sum = 0.f;
        for (int d = h * 150 + lane; d < (h + 1) * 150; d += 32)
            sum += Q[l * DD + d] * Kb[nl * DD + d];
        for (int o = 16; o; o >>= 1) sum += __shfl_down_sync(0xffffffff, sum, o);
        if (lane == 0) sc[wrp] = sum * rsqrtf(150.f);
    }
    __syncthreads();
    if (tid < 2) {
        int h = tid;
        float m = fmaxf(sc[h * 3], fmaxf(sc[h * 3 + 1], sc[h * 3 + 2]));
        float e0 = expf(sc[h * 3] - m), e1 = expf(sc[h * 3 + 1] - m), e2 = expf(sc[h * 3 + 2] - m);
        float inv = 1.f / (e0 + e1 + e2);
        alpha[h * 3] = e0 * inv; alpha[h * 3 + 1] = e1 * inv; alpha[h * 3 + 2] = e2 * inv;
    }
    __syncthreads();
    if (tid < DD) {
        int h = tid / 150;
        float s = 0.f;
#pragma unroll
        for (int w = 0; w < 3; w++) {
            int nl = max(0, min(LL - 1, l + w - 1));
            s += alpha[h * 3 + w] * V[nl * DD + tid];
        }
        ao[l * DD + tid] = s;
    }
}

// ---------------- ||relatt_out|| per row (reads feat[:,300:600]) ----------------
__global__ void rnorm_kernel(const float* __restrict__ feat, float* __restrict__ rnorm)
{
    int l = blockIdx.x; int tid = threadIdx.x;
    __shared__ float red[10];
    float v = 0.f;
    if (tid < DD) { float x = feat[l * FEATD + 300 + tid]; v = x * x; }
    for (int o = 16; o; o >>= 1) v += __shfl_down_sync(0xffffffff, v, o);
    if ((tid & 31) == 0) red[tid >> 5] = v;
    __syncthreads();
    if (tid == 0) { float s = 0.f; for (int i = 0; i < 10; i++) s += red[i]; rnorm[l] = sqrtf(s); }
}

// ---------------- concept-graph dual attention ----------------
__global__ void __launch_bounds__(512) concept_kernel(
    const int* __restrict__ src_ids, const int* __restrict__ dst_ids,
    const float* __restrict__ cw, const float* __restrict__ cs,
    const float* __restrict__ table, const float* __restrict__ rvecs,
    const float* __restrict__ feat, const float* __restrict__ rnorm,
    float* __restrict__ nodes, float* __restrict__ nscore, float* __restrict__ nmask)
{
    int s = blockIdx.x, l = blockIdx.y, g = blockIdx.z;
    int tid = threadIdx.x;
    int base3 = (g * LL + l) * SS + s;
    int base4 = base3 * KK;
    int nidx = l * NNODE + g * SS + s;
    int sid = src_ids[base3];
    if (sid < 0) {
        if (tid == 0) { nscore[nidx] = NEGV; nmask[nidx] = 0.f; }
        return;
    }
    __shared__ float dsh[KK][DD];
    __shared__ float srcsh[DD], rsh[DD], relsh[DD];
    __shared__ int ids[KK];
    __shared__ float wgt[KK], sen[KK];
    __shared__ float avals[KK], nvals[KK], bvals[KK], coef[KK];
    __shared__ float redbuf[16];

    if (tid < KK) {
        ids[tid] = dst_ids[base4 + tid];
        wgt[tid] = cw[base4 + tid];
        sen[tid] = cs[base4 + tid];
    }
    for (int t = tid; t < DD; t += blockDim.x) {
        srcsh[t] = table[sid * DD + t];
        rsh[t] = rvecs[g * DD + t];
        relsh[t] = feat[l * FEATD + 300 + t];
    }
    __syncthreads();
    for (int idx = tid; idx < KK * DD; idx += blockDim.x) {
        int k = idx / DD, d = idx - k * DD;
        int id = ids[k];
        dsh[k][d] = (id >= 0) ? table[id * DD + d] : 0.f;
    }
    __syncthreads();
    int wrp = tid >> 5, lane = tid & 31;
    {   // one warp per dst-k: three 300-dots
        int k = wrp;
        float a = 0.f, n = 0.f, b = 0.f;
        for (int d = lane; d < DD; d += 32) {
            float dv = dsh[k][d];
            a += relsh[d] * dv;
            n += dv * dv;
            b += srcsh[d] * rsh[d] * dv;
        }
        for (int o = 16; o; o >>= 1) {
            a += __shfl_down_sync(0xffffffff, a, o);
            n += __shfl_down_sync(0xffffffff, n, o);
            b += __shfl_down_sync(0xffffffff, b, o);
        }
        if (lane == 0) { avals[k] = a; nvals[k] = n; bvals[k] = b; }
    }
    __syncthreads();
    if (tid == 0) {
        float rn = rnorm[l];
        float omega[KK];
        float m1 = -1e30f;
        for (int k = 0; k < KK; k++) {
            omega[k] = 0.f;
            if (ids[k] >= 0) {
                float cosv = fabsf(avals[k]) / (rn * sqrtf(nvals[k]) + 1e-8f);
                omega[k] = 0.5f * wgt[k] * cosv + 0.5f * fabsf(sen[k]);
                m1 = fmaxf(m1, omega[k]);
            }
        }
        float a1[KK]; float den = 0.f;
        for (int k = 0; k < KK; k++) { a1[k] = (ids[k] >= 0) ? expf(omega[k] - m1) : 0.f; den += a1[k]; }
        float inv = (den > 0.f) ? 1.f / den : 0.f;
        float sarr[KK]; float m2 = -1e30f;
        for (int k = 0; k < KK; k++) {
            a1[k] *= inv;
            sarr[k] = a1[k] * bvals[k];
            if (ids[k] >= 0) m2 = fmaxf(m2, sarr[k]);
        }
        float den2 = 0.f; float a2[KK];
        for (int k = 0; k < KK; k++) { a2[k] = (ids[k] >= 0) ? expf(sarr[k] - m2) : 0.f; den2 += a2[k]; }
        float inv2 = (den2 > 0.f) ? 1.f / den2 : 0.f;
        for (int k = 0; k < KK; k++) coef[k] = a1[k] * a2[k] * inv2;
    }
    __syncthreads();
    float part = 0.f;
    if (tid < DD) {
        float sum = 0.f;
#pragma unroll
        for (int k = 0; k < KK; k++) sum += coef[k] * dsh[k][tid];
        float nodeval = srcsh[tid] + rsh[tid] * sum;
        nodes[nidx * DD + tid] = nodeval;
        part = nodeval * relsh[tid];
    }
    for (int o = 16; o; o >>= 1) part += __shfl_down_sync(0xffffffff, part, o);
    if (lane == 0) redbuf[wrp] = part;
    __syncthreads();
    if (tid == 0) {
        float sc = 0.f;
        for (int i = 0; i < 16; i++) sc += redbuf[i];
        nscore[nidx] = sc; nmask[nidx] = 1.f;
    }
}

// ---------------- node softmax + sym (into feat[:,600:900]) ----------------
__global__ void sym_kernel(const float* __restrict__ nodes, const float* __restrict__ nscore,
                           const float* __restrict__ nmask, float* __restrict__ feat)
{
    int l = blockIdx.x; int tid = threadIdx.x;
    __shared__ float att[NNODE];
    __shared__ int anyv;
    if (tid == 0) {
        float m = -1e30f; int any = 0;
        for (int n = 0; n < NNODE; n++)
            if (nmask[l * NNODE + n] > 0.5f) { any = 1; m = fmaxf(m, nscore[l * NNODE + n]); }
        float den = 0.f;
        for (int n = 0; n < NNODE; n++) {
            float a = (nmask[l * NNODE + n] > 0.5f) ? expf(nscore[l * NNODE + n] - m) : 0.f;
            att[n] = a; den += a;
        }
        float inv = any ? 1.f / den : 0.f;
        for (int n = 0; n < NNODE; n++) att[n] *= inv;
        anyv = any;
    }
    __syncthreads();
    if (tid < DD) {
        float sum = 0.f;
        if (anyv) {
            for (int n = 0; n < NNODE; n++) {
                float a = att[n];
                if (a != 0.f) sum += a * nodes[(l * NNODE + n) * DD + tid];
            }
        }
        feat[l * FEATD + 600 + tid] = sum;
    }
}

// ---------------- final logits + log_softmax ----------------
__global__ void final_kernel(const float* __restrict__ h, const float* __restrict__ Wout,
                             const float* __restrict__ bout, float* __restrict__ out)
{
    int l = blockIdx.x; int lane = threadIdx.x;  // blockDim = 32
    __shared__ float logits[CC];
    for (int c = 0; c < CC; c++) {
        float sum = 0.f;
        for (int d = lane; d < DD; d += 32) sum += h[l * DD + d] * Wout[d * CC + c];
        for (int o = 16; o; o >>= 1) sum += __shfl_down_sync(0xffffffff, sum, o);
        if (lane == 0) logits[c] = sum + bout[c];
    }
    __syncwarp();
    if (lane == 0) {
        float m = -1e30f;
        for (int c = 0; c < CC; c++) m = fmaxf(m, logits[c]);
        float den = 0.f;
        for (int c = 0; c < CC; c++) den += expf(logits[c] - m);
        float lden = logf(den);
        for (int c = 0; c < CC; c++) out[l * CC + c] = logits[c] - m - lden;
    }
}

extern "C" void kernel_launch(void* const* d_in, const int* in_sizes, int n_in,
                              void* d_out, int out_size)
{
    const float* utt     = (const float*)d_in[0];
    const int*   str_src = (const int*)d_in[1];
    const int*   str_dst = (const int*)d_in[2];
    const int*   str_et  = (const int*)d_in[3];
    const int*   c_src   = (const int*)d_in[4];
    const int*   c_dst   = (const int*)d_in[5];
    const float* c_w     = (const float*)d_in[6];
    const float* c_s     = (const float*)d_in[7];
    const float* table   = (const float*)d_in[8];
    const float* W_basis = (const float*)d_in[9];
    const float* comp    = (const float*)d_in[10];
    const float* W_self  = (const float*)d_in[11];
    const float* b_rgcn  = (const float*)d_in[12];
    const float* Wq      = (const float*)d_in[13];
    const float* Wk      = (const float*)d_in[14];
    const float* Wv      = (const float*)d_in[15];
    const float* Wo      = (const float*)d_in[16];
    const float* rvecs   = (const float*)d_in[17];
    const float* W_fuse  = (const float*)d_in[18];
    const float* b_fuse  = (const float*)d_in[19];
    const float* W_out   = (const float*)d_in[20];
    const float* b_out   = (const float*)d_in[21];
    float* out = (float*)d_out;

    float* base;
    cudaGetSymbolAddress((void**)&base, g_scratch);
    float* P0     = base;
    float* P1     = base + 76800;
    float* Qb     = base + 153600;
    float* Kb     = base + 230400;
    float* Vb     = base + 307200;
    float* ao     = base + 384000;
    float* feat   = base + 460800;
    float* rn     = base + 691200;
    float* nodes  = base + 691456;
    float* nscore = base + 4377856;
    float* nmask  = base + 4390144;
    float* hb     = base + 4402432;

    const int ROWS = 8;
    int nblk = (LL + ROWS - 1) / ROWS;  // 32
    size_t sh300 = ROWS * 300 * sizeof(float);
    size_t sh900 = ROWS * 900 * sizeof(float);

    rowgemm_kernel<8><<<nblk, 320, sh300>>>(utt, W_basis,          nullptr, P0,       LL, 300, 300, 300, 300, 0);
    rowgemm_kernel<8><<<nblk, 320, sh300>>>(utt, W_basis + 90000,  nullptr, P1,       LL, 300, 300, 300, 300, 0);
    rowgemm_kernel<8><<<nblk, 320, sh300>>>(utt, Wq,               nullptr, Qb,       LL, 300, 300, 300, 300, 0);
    rowgemm_kernel<8><<<nblk, 320, sh300>>>(utt, Wk,               nullptr, Kb,       LL, 300, 300, 300, 300, 0);
    rowgemm_kernel<8><<<nblk, 320, sh300>>>(utt, Wv,               nullptr, Vb,       LL, 300, 300, 300, 300, 0);
    rowgemm_kernel<8><<<nblk, 320, sh300>>>(utt, W_self,           b_rgcn,  feat,     LL, 300, 300, 300, 900, 0);
    edge_kernel<<<(2048 * DD + 255) / 256, 256>>>(str_src, str_dst, str_et, comp, P0, P1, feat, 2048);
    relatt_kernel<<<LL, 320>>>(Qb, Kb, Vb, ao);
    rowgemm_kernel<8><<<nblk, 320, sh300>>>(ao, Wo, nullptr, feat + 300, LL, 300, 300, 300, 900, 0);
    rnorm_kernel<<<LL, 320>>>(feat, rn);
    dim3 cgrid(SS, LL, 3);
    concept_kernel<<<cgrid, 512>>>(c_src, c_dst, c_w, c_s, table, rvecs, feat, rn, nodes, nscore, nmask);
    sym_kernel<<<LL, 320>>>(nodes, nscore, nmask, feat);
    rowgemm_kernel<8><<<nblk, 320, sh900>>>(feat, W_fuse, b_fuse, hb, LL, 900, 300, 900, 300, 1);
    final_kernel<<<LL, 32>>>(hb, W_out, b_out, out);
}

// round 9
// speedup vs baseline: 1.8590x; 1.8590x over previous
#include <cuda_runtime.h>
#include <math.h>

#define LL 256
#define DD 300
#define SS 16
#define KK 16
#define NNODE 48
#define CC 7
#define FEATD 900
#define NEGV -1000000000.0f

// scratch layout (floats):
// P0:0  P1:76800  Q:153600  K:230400  V:307200  ao:384000
// feat:460800 (256*900)  rnorm:691200  nodes:691456 (256*48*300)
// nscore:4377856  nmask:4390144  hpart:4402432 (3*76800)  end:4632832
__device__ __align__(16) float g_scratch[4632832];

// ---------------- GEMM inner core: 8-wide K unroll for MLP ----------------
template<int ROWS>
__device__ __forceinline__ void gemm_core(const float* __restrict__ xs,
                                          const float* __restrict__ W,
                                          int Kdim, int N, int tid, float* acc)
{
    int i = 0;
    for (; i + 8 <= Kdim; i += 8) {
        float w[8];
#pragma unroll
        for (int u = 0; u < 8; u++) w[u] = __ldg(&W[(i + u) * N + tid]);
#pragma unroll
        for (int u = 0; u < 8; u++) {
#pragma unroll
            for (int r = 0; r < ROWS; r++) acc[r] += xs[r * Kdim + i + u] * w[u];
        }
    }
    for (; i < Kdim; i++) {
        float w = __ldg(&W[i * N + tid]);
#pragma unroll
        for (int r = 0; r < ROWS; r++) acc[r] += xs[r * Kdim + i] * w;
    }
}

// ---------------- batched 6-way utt projection ----------------
// y=0: P0=utt@Wb0   y=1: P1=utt@Wb1   y=2..4: Q/K/V   y=5: feat[:,0:300]=utt@W_self+b
__global__ void __launch_bounds__(320) mega6_kernel(
    const float* __restrict__ utt,
    const float* __restrict__ W_basis, const float* __restrict__ Wq,
    const float* __restrict__ Wk, const float* __restrict__ Wv,
    const float* __restrict__ W_self, const float* __restrict__ b_rgcn,
    float* __restrict__ P0, float* __restrict__ P1, float* __restrict__ Qb,
    float* __restrict__ Kb, float* __restrict__ Vb, float* __restrict__ feat)
{
    __shared__ float xs[8 * DD];
    int row0 = blockIdx.x * 8;
    int y = blockIdx.y;
    int tid = threadIdx.x;
    for (int idx = tid; idx < 8 * DD; idx += blockDim.x) {
        int r = idx / DD, i = idx - r * DD;
        xs[idx] = utt[(row0 + r) * DD + i];
    }
    __syncthreads();
    if (tid >= DD) return;

    const float* W;
    float* out;
    int ldo = DD;
    float bias = 0.f;
    switch (y) {
        case 0: W = W_basis;           out = P0;   break;
        case 1: W = W_basis + 90000;   out = P1;   break;
        case 2: W = Wq;                out = Qb;   break;
        case 3: W = Wk;                out = Kb;   break;
        case 4: W = Wv;                out = Vb;   break;
        default: W = W_self;           out = feat; ldo = FEATD; bias = b_rgcn[tid]; break;
    }
    float acc[8];
#pragma unroll
    for (int r = 0; r < 8; r++) acc[r] = 0.f;
    gemm_core<8>(xs, W, DD, DD, tid, acc);
#pragma unroll
    for (int r = 0; r < 8; r++) out[(row0 + r) * ldo + tid] = acc[r] + bias;
}

// ---------------- generic multi-row matvec (used for Wo) ----------------
__global__ void __launch_bounds__(320) rowgemm_kernel(
    const float* __restrict__ X, const float* __restrict__ W,
    float* __restrict__ out, int Kdim, int N, int ldx, int ldo)
{
    extern __shared__ float xs[]; // 8*Kdim
    int row0 = blockIdx.x * 8;
    int tid = threadIdx.x;
    for (int idx = tid; idx < 8 * Kdim; idx += blockDim.x) {
        int r = idx / Kdim, i = idx - r * Kdim;
        xs[idx] = X[(row0 + r) * ldx + i];
    }
    __syncthreads();
    if (tid >= N) return;
    float acc[8];
#pragma unroll
    for (int r = 0; r < 8; r++) acc[r] = 0.f;
    gemm_core<8>(xs, W, Kdim, N, tid, acc);
#pragma unroll
    for (int r = 0; r < 8; r++) out[(row0 + r) * ldo + tid] = acc[r];
}

// ---------------- fuse GEMM, K split in 3 chunks: hpart[c] = feat[:,300c:300c+300] @ Wfuse[300c:...] ----------------
__global__ void __launch_bounds__(320) fuse_kernel(
    const float* __restrict__ feat, const float* __restrict__ Wfuse,
    float* __restrict__ hpart)
{
    __shared__ float xs[8 * DD];
    int row0 = blockIdx.x * 8;
    int c = blockIdx.y;
    int tid = threadIdx.x;
    for (int idx = tid; idx < 8 * DD; idx += blockDim.x) {
        int r = idx / DD, i = idx - r * DD;
        xs[idx] = feat[(row0 + r) * FEATD + c * DD + i];
    }
    __syncthreads();
    if (tid >= DD) return;
    float acc[8];
#pragma unroll
    for (int r = 0; r < 8; r++) acc[r] = 0.f;
    gemm_core<8>(xs, Wfuse + c * 90000, DD, DD, tid, acc);
#pragma unroll
    for (int r = 0; r < 8; r++) hpart[c * 76800 + (row0 + r) * DD + tid] = acc[r];
}

// ---------------- RGCN edge scatter ----------------
__global__ void edge_kernel(const int* __restrict__ src, const int* __restrict__ dst,
                            const int* __restrict__ etype, const float* __restrict__ comp,
                            const float* __restrict__ P0, const float* __restrict__ P1,
                            float* __restrict__ feat, int E)
{
    int idx = blockIdx.x * blockDim.x + threadIdx.x;
    if (idx >= E * DD) return;
    int e = idx / DD, d = idx - e * DD;
    int s = src[e], t = dst[e], r = etype[e];
    float c0 = comp[r * 2], c1 = comp[r * 2 + 1];
    float v = c0 * P0[s * DD + d] + c1 * P1[s * DD + d];
    atomicAdd(&feat[t * FEATD + d], v);
}

// ---------------- windowed 2-head attention (center query only) ----------------
__global__ void relatt_kernel(const float* __restrict__ Q, const float* __restrict__ Kb,
                              const float* __restrict__ V, float* __restrict__ ao)
{
    int l = blockIdx.x;
    int tid = threadIdx.x;
    int wrp = tid >> 5, lane = tid & 31;
    __shared__ float sc[6];
    __shared__ float alpha[6];
    if (wrp < 6) {
        int h = wrp / 3, w = wrp % 3;
        int nl = l + w - 1; nl = max(0, min(LL - 1, nl));
        float sum = 0.f;
        for (int d = h * 150 + lane; d < (h + 1) * 150; d += 32)
            sum += Q[l * DD + d] * Kb[nl * DD + d];
        for (int o = 16; o; o >>= 1) sum += __shfl_down_sync(0xffffffff, sum, o);
        if (lane == 0) sc[wrp] = sum * rsqrtf(150.f);
    }
    __syncthreads();
    if (tid < 2) {
        int h = tid;
        float m = fmaxf(sc[h * 3], fmaxf(sc[h * 3 + 1], sc[h * 3 + 2]));
        float e0 = expf(sc[h * 3] - m), e1 = expf(sc[h * 3 + 1] - m), e2 = expf(sc[h * 3 + 2] - m);
        float inv = 1.f / (e0 + e1 + e2);
        alpha[h * 3] = e0 * inv; alpha[h * 3 + 1] = e1 * inv; alpha[h * 3 + 2] = e2 * inv;
    }
    __syncthreads();
    if (tid < DD) {
        int h = tid / 150;
        float s = 0.f;
#pragma unroll
        for (int w = 0; w < 3; w++) {
            int nl = max(0, min(LL - 1, l + w - 1));
            s += alpha[h * 3 + w] * V[nl * DD + tid];
        }
        ao[l * DD + tid] = s;
    }
}

// ---------------- ||relatt_out|| per row (reads feat[:,300:600]) ----------------
__global__ void rnorm_kernel(const float* __restrict__ feat, float* __restrict__ rnorm)
{
    int l = blockIdx.x; int tid = threadIdx.x;
    __shared__ float red[10];
    float v = 0.f;
    if (tid < DD) { float x = feat[l * FEATD + 300 + tid]; v = x * x; }
    for (int o = 16; o; o >>= 1) v += __shfl_down_sync(0xffffffff, v, o);
    if ((tid & 31) == 0) red[tid >> 5] = v;
    __syncthreads();
    if (tid == 0) { float s = 0.f; for (int i = 0; i < 10; i++) s += red[i]; rnorm[l] = sqrtf(s); }
}

// ---------------- concept-graph dual attention ----------------
__global__ void __launch_bounds__(512) concept_kernel(
    const int* __restrict__ src_ids, const int* __restrict__ dst_ids,
    const float* __restrict__ cw, const float* __restrict__ cs,
    const float* __restrict__ table, const float* __restrict__ rvecs,
    const float* __restrict__ feat, const float* __restrict__ rnorm,
    float* __restrict__ nodes, float* __restrict__ nscore, float* __restrict__ nmask)
{
    int s = blockIdx.x, l = blockIdx.y, g = blockIdx.z;
    int tid = threadIdx.x;
    int base3 = (g * LL + l) * SS + s;
    int base4 = base3 * KK;
    int nidx = l * NNODE + g * SS + s;
    int sid = src_ids[base3];
    if (sid < 0) {
        if (tid == 0) { nscore[nidx] = NEGV; nmask[nidx] = 0.f; }
        return;
    }
    __shared__ __align__(16) float dsh[KK][DD];
    __shared__ __align__(16) float srcsh[DD], rsh[DD], relsh[DD];
    __shared__ int ids[KK];
    __shared__ float wgt[KK], sen[KK];
    __shared__ float avals[KK], nvals[KK], bvals[KK], coef[KK];
    __shared__ float redbuf[16];

    if (tid < KK) {
        ids[tid] = dst_ids[base4 + tid];
        wgt[tid] = cw[base4 + tid];
        sen[tid] = cs[base4 + tid];
    }
    // vectorized fills: 300 floats = 75 float4
    const float4* t4 = reinterpret_cast<const float4*>(table);
    const float4* r4 = reinterpret_cast<const float4*>(rvecs);
    const float4* f4 = reinterpret_cast<const float4*>(feat);
    if (tid < 75) {
        reinterpret_cast<float4*>(srcsh)[tid] = t4[sid * 75 + tid];
    } else if (tid < 150) {
        int j = tid - 75;
        reinterpret_cast<float4*>(rsh)[j] = r4[g * 75 + j];
    } else if (tid < 225) {
        int j = tid - 150;
        reinterpret_cast<float4*>(relsh)[j] = f4[(l * FEATD + 300) / 4 + j];
    }
    __syncthreads();
    for (int idx = tid; idx < KK * 75; idx += blockDim.x) {
        int k = idx / 75, j = idx - k * 75;
        int id = ids[k];
        float4 v = (id >= 0) ? t4[id * 75 + j] : make_float4(0.f, 0.f, 0.f, 0.f);
        reinterpret_cast<float4*>(&dsh[k][0])[j] = v;
    }
    __syncthreads();
    int wrp = tid >> 5, lane = tid & 31;
    {   // one warp per dst-k: three 300-dots
        int k = wrp;
        float a = 0.f, n = 0.f, b = 0.f;
        for (int d = lane; d < DD; d += 32) {
            float dv = dsh[k][d];
            a += relsh[d] * dv;
            n += dv * dv;
            b += srcsh[d] * rsh[d] * dv;
        }
        for (int o = 16; o; o >>= 1) {
            a += __shfl_down_sync(0xffffffff, a, o);
            n += __shfl_down_sync(0xffffffff, n, o);
            b += __shfl_down_sync(0xffffffff, b, o);
        }
        if (lane == 0) { avals[k] = a; nvals[k] = n; bvals[k] = b; }
    }
    __syncthreads();
    if (tid == 0) {
        float rn = rnorm[l];
        float omega[KK];
        float m1 = -1e30f;
        for (int k = 0; k < KK; k++) {
            omega[k] = 0.f;
            if (ids[k] >= 0) {
                float cosv = fabsf(avals[k]) / (rn * sqrtf(nvals[k]) + 1e-8f);
                omega[k] = 0.5f * wgt[k] * cosv + 0.5f * fabsf(sen[k]);
                m1 = fmaxf(m1, omega[k]);
            }
        }
        float a1[KK]; float den = 0.f;
        for (int k = 0; k < KK; k++) { a1[k] = (ids[k] >= 0) ? expf(omega[k] - m1) : 0.f; den += a1[k]; }
        float inv = (den > 0.f) ? 1.f / den : 0.f;
        float sarr[KK]; float m2 = -1e30f;
        for (int k = 0; k < KK; k++) {
            a1[k] *= inv;
            sarr[k] = a1[k] * bvals[k];
            if (ids[k] >= 0) m2 = fmaxf(m2, sarr[k]);
        }
        float den2 = 0.f; float a2[KK];
        for (int k = 0; k < KK; k++) { a2[k] = (ids[k] >= 0) ? expf(sarr[k] - m2) : 0.f; den2 += a2[k]; }
        float inv2 = (den2 > 0.f) ? 1.f / den2 : 0.f;
        for (int k = 0; k < KK; k++) coef[k] = a1[k] * a2[k] * inv2;
    }
    __syncthreads();
    float part = 0.f;
    if (tid < DD) {
        float sum = 0.f;
#pragma unroll
        for (int k = 0; k < KK; k++) sum += coef[k] * dsh[k][tid];
        float nodeval = srcsh[tid] + rsh[tid] * sum;
        nodes[nidx * DD + tid] = nodeval;
        part = nodeval * relsh[tid];
    }
    for (int o = 16; o; o >>= 1) part += __shfl_down_sync(0xffffffff, part, o);
    if (lane == 0) redbuf[wrp] = part;
    __syncthreads();
    if (tid == 0) {
        float sc = 0.f;
        for (int i = 0; i < 16; i++) sc += redbuf[i];
        nscore[nidx] = sc; nmask[nidx] = 1.f;
    }
}

// ---------------- node softmax + sym (into feat[:,600:900]) ----------------
__global__ void sym_kernel(const float* __restrict__ nodes, const float* __restrict__ nscore,
                           const float* __restrict__ nmask, float* __restrict__ feat)
{
    int l = blockIdx.x; int tid = threadIdx.x;
    __shared__ float att[NNODE];
    __shared__ int anyv;
    if (tid == 0) {
        float m = -1e30f; int any = 0;
        for (int n = 0; n < NNODE; n++)
            if (nmask[l * NNODE + n] > 0.5f) { any = 1; m = fmaxf(m, nscore[l * NNODE + n]); }
        float den = 0.f;
        for (int n = 0; n < NNODE; n++) {
            float a = (nmask[l * NNODE + n] > 0.5f) ? expf(nscore[l * NNODE + n] - m) : 0.f;
            att[n] = a; den += a;
        }
        float inv = any ? 1.f / den : 0.f;
        for (int n = 0; n < NNODE; n++) att[n] *= inv;
        anyv = any;
    }
    __syncthreads();
    if (tid < DD) {
        float sum = 0.f;
        if (anyv) {
            for (int n = 0; n < NNODE; n++) {
                float a = att[n];
                if (a != 0.f) sum += a * nodes[(l * NNODE + n) * DD + tid];
            }
        }
        feat[l * FEATD + 600 + tid] = sum;
    }
}

// ---------------- final: sum K-chunks + bias + relu, logits, log_softmax ----------------
__global__ void final_kernel(const float* __restrict__ hp, const float* __restrict__ bfuse,
                             const float* __restrict__ Wout, const float* __restrict__ bout,
                             float* __restrict__ out)
{
    int l = blockIdx.x; int lane = threadIdx.x;  // blockDim = 32
    float hv[10];
#pragma unroll
    for (int j = 0; j < 10; j++) {
        int d = lane + 32 * j;
        float v = 0.f;
        if (d < DD) {
            v = bfuse[d] + hp[l * DD + d] + hp[76800 + l * DD + d] + hp[153600 + l * DD + d];
            v = fmaxf(v, 0.f);
        }
        hv[j] = v;
    }
    __shared__ float logits[CC];
    for (int c = 0; c < CC; c++) {
        float sum = 0.f;
#pragma unroll
        for (int j = 0; j < 10; j++) {
            int d = lane + 32 * j;
            if (d < DD) sum += hv[j] * Wout[d * CC + c];
        }
        for (int o = 16; o; o >>= 1) sum += __shfl_down_sync(0xffffffff, sum, o);
        if (lane == 0) logits[c] = sum + bout[c];
    }
    __syncwarp();
    if (lane == 0) {
        float m = -1e30f;
        for (int c = 0; c < CC; c++) m = fmaxf(m, logits[c]);
        float den = 0.f;
        for (int c = 0; c < CC; c++) den += expf(logits[c] - m);
        float lden = logf(den);
        for (int c = 0; c < CC; c++) out[l * CC + c] = logits[c] - m - lden;
    }
}

extern "C" void kernel_launch(void* const* d_in, const int* in_sizes, int n_in,
                              void* d_out, int out_size)
{
    const float* utt     = (const float*)d_in[0];
    const int*   str_src = (const int*)d_in[1];
    const int*   str_dst = (const int*)d_in[2];
    const int*   str_et  = (const int*)d_in[3];
    const int*   c_src   = (const int*)d_in[4];
    const int*   c_dst   = (const int*)d_in[5];
    const float* c_w     = (const float*)d_in[6];
    const float* c_s     = (const float*)d_in[7];
    const float* table   = (const float*)d_in[8];
    const float* W_basis = (const float*)d_in[9];
    const float* comp    = (const float*)d_in[10];
    const float* W_self  = (const float*)d_in[11];
    const float* b_rgcn  = (const float*)d_in[12];
    const float* Wq      = (const float*)d_in[13];
    const float* Wk      = (const float*)d_in[14];
    const float* Wv      = (const float*)d_in[15];
    const float* Wo      = (const float*)d_in[16];
    const float* rvecs   = (const float*)d_in[17];
    const float* W_fuse  = (const float*)d_in[18];
    const float* b_fuse  = (const float*)d_in[19];
    const float* W_out   = (const float*)d_in[20];
    const float* b_out   = (const float*)d_in[21];
    float* out = (float*)d_out;

    float* base;
    cudaGetSymbolAddress((void**)&base, g_scratch);
    float* P0     = base;
    float* P1     = base + 76800;
    float* Qb     = base + 153600;
    float* Kb     = base + 230400;
    float* Vb     = base + 307200;
    float* ao     = base + 384000;
    float* feat   = base + 460800;
    float* rn     = base + 691200;
    float* nodes  = base + 691456;
    float* nscore = base + 4377856;
    float* nmask  = base + 4390144;
    float* hpart  = base + 4402432;

    dim3 mgrid(32, 6);
    mega6_kernel<<<mgrid, 320>>>(utt, W_basis, Wq, Wk, Wv, W_self, b_rgcn,
                                 P0, P1, Qb, Kb, Vb, feat);
    edge_kernel<<<(2048 * DD + 255) / 256, 256>>>(str_src, str_dst, str_et, comp, P0, P1, feat, 2048);
    relatt_kernel<<<LL, 320>>>(Qb, Kb, Vb, ao);
    rowgemm_kernel<<<32, 320, 8 * DD * sizeof(float)>>>(ao, Wo, feat + 300, DD, DD, DD, FEATD);
    rnorm_kernel<<<LL, 320>>>(feat, rn);
    dim3 cgrid(SS, LL, 3);
    concept_kernel<<<cgrid, 512>>>(c_src, c_dst, c_w, c_s, table, rvecs, feat, rn, nodes, nscore, nmask);
    sym_kernel<<<LL, 320>>>(nodes, nscore, nmask, feat);
    dim3 fgrid(32, 3);
    fuse_kernel<<<fgrid, 320>>>(feat, W_fuse, hpart);
    final_kernel<<<LL, 32>>>(hpart, b_fuse, W_out, b_out, out);
}

// round 12
// speedup vs baseline: 1.8731x; 1.0076x over previous
#include <cuda_runtime.h>
#include <math.h>

#define LL 256
#define DD 300
#define SS 16
#define KK 16
#define NNODE 48
#define CC 7
#define FEATD 900
#define NEGV -1000000000.0f
#define KT 25   // K-tile for smem-staged GEMM (300 = 12*25)

// scratch layout (floats):
// P0:0  P1:76800  Q:153600  K:230400  V:307200  ao:384000
// feat:460800 (256*900)  rnorm:691200  nodes:691456 (256*48*300)
// nscore:4377856  nmask:4390144  hpart:4402432 (3*76800)  end:4632832
__device__ __align__(16) float g_scratch[4632832];

// ---------------- smem-tiled GEMM core ----------------
// Computes acc[r] = sum_i X[(row0+r)*ldx + i] * W[i*300 + tid] for r=0..7, K=N=300.
// xs: 2400 floats (X rows transposed: xs[i*8+r]); wt: KT*300 floats.
// ALL 320 threads must call (has __syncthreads); tid>=300 contribute loads only.
__device__ __forceinline__ void gemm300_core(
    const float* __restrict__ Xrow0, int ldx,
    const float* __restrict__ W,
    float* xs, float* wt, int tid, float* acc)
{
    // stage 8 X rows, transposed (one-time)
    for (int idx = tid; idx < 600; idx += 320) {   // 8 rows * 75 float4
        int r = idx / 75, j = idx - r * 75;
        float4 v = *reinterpret_cast<const float4*>(Xrow0 + r * ldx + 4 * j);
        int i = 4 * j;
        xs[i * 8 + r] = v.x; xs[(i + 1) * 8 + r] = v.y;
        xs[(i + 2) * 8 + r] = v.z; xs[(i + 3) * 8 + r] = v.w;
    }
#pragma unroll
    for (int r = 0; r < 8; r++) acc[r] = 0.f;

    for (int t = 0; t < 300; t += KT) {
        // stage W tile [t..t+KT) x 300, coalesced float4
        const float4* wsrc = reinterpret_cast<const float4*>(W + t * 300);
        float4* wdst = reinterpret_cast<float4*>(wt);
        for (int j = tid; j < KT * 75; j += 320) wdst[j] = wsrc[j];
        __syncthreads();
        if (tid < 300) {
#pragma unroll
            for (int i = 0; i < KT; i++) {
                float w = wt[i * 300 + tid];
                float4 xa = *reinterpret_cast<const float4*>(&xs[(t + i) * 8]);
                float4 xb = *reinterpret_cast<const float4*>(&xs[(t + i) * 8 + 4]);
                acc[0] += xa.x * w; acc[1] += xa.y * w;
                acc[2] += xa.z * w; acc[3] += xa.w * w;
                acc[4] += xb.x * w; acc[5] += xb.y * w;
                acc[6] += xb.z * w; acc[7] += xb.w * w;
            }
        }
        __syncthreads();
    }
}

// ---------------- batched 6-way utt projection ----------------
__global__ void __launch_bounds__(320) mega6_kernel(
    const float* __restrict__ utt,
    const float* __restrict__ W_basis, const float* __restrict__ Wq,
    const float* __restrict__ Wk, const float* __restrict__ Wv,
    const float* __restrict__ W_self, const float* __restrict__ b_rgcn,
    float* __restrict__ P0, float* __restrict__ P1, float* __restrict__ Qb,
    float* __restrict__ Kb, float* __restrict__ Vb, float* __restrict__ feat)
{
    __shared__ __align__(16) float xs[8 * DD];
    __shared__ __align__(16) float wt[KT * DD];
    int row0 = blockIdx.x * 8;
    int y = blockIdx.y;
    int tid = threadIdx.x;

    const float* W;
    float* out;
    int ldo = DD;
    int use_bias = 0;
    switch (y) {
        case 0: W = W_basis;          out = P0;   break;
        case 1: W = W_basis + 90000;  out = P1;   break;
        case 2: W = Wq;               out = Qb;   break;
        case 3: W = Wk;               out = Kb;   break;
        case 4: W = Wv;               out = Vb;   break;
        default: W = W_self;          out = feat; ldo = FEATD; use_bias = 1; break;
    }
    float acc[8];
    gemm300_core(utt + row0 * DD, DD, W, xs, wt, tid, acc);
    if (tid < DD) {
        float bias = use_bias ? b_rgcn[tid] : 0.f;
#pragma unroll
        for (int r = 0; r < 8; r++) out[(row0 + r) * ldo + tid] = acc[r] + bias;
    }
}

// ---------------- Wo matvec ----------------
__global__ void __launch_bounds__(320) rowgemm_kernel(
    const float* __restrict__ X, const float* __restrict__ W,
    float* __restrict__ out, int ldx, int ldo)
{
    __shared__ __align__(16) float xs[8 * DD];
    __shared__ __align__(16) float wt[KT * DD];
    int row0 = blockIdx.x * 8;
    int tid = threadIdx.x;
    float acc[8];
    gemm300_core(X + row0 * ldx, ldx, W, xs, wt, tid, acc);
    if (tid < DD) {
#pragma unroll
        for (int r = 0; r < 8; r++) out[(row0 + r) * ldo + tid] = acc[r];
    }
}

// ---------------- fuse GEMM, K split in 3 chunks ----------------
__global__ void __launch_bounds__(320) fuse_kernel(
    const float* __restrict__ feat, const float* __restrict__ Wfuse,
    float* __restrict__ hpart)
{
    __shared__ __align__(16) float xs[8 * DD];
    __shared__ __align__(16) float wt[KT * DD];
    int row0 = blockIdx.x * 8;
    int c = blockIdx.y;
    int tid = threadIdx.x;
    float acc[8];
    gemm300_core(feat + row0 * FEATD + c * DD, FEATD, Wfuse + c * 90000, xs, wt, tid, acc);
    if (tid < DD) {
#pragma unroll
        for (int r = 0; r < 8; r++) hpart[c * 76800 + (row0 + r) * DD + tid] = acc[r];
    }
}

// ---------------- RGCN edge scatter ----------------
__global__ void edge_kernel(const int* __restrict__ src, const int* __restrict__ dst,
                            const int* __restrict__ etype, const float* __restrict__ comp,
                            const float* __restrict__ P0, const float* __restrict__ P1,
                            float* __restrict__ feat, int E)
{
    int idx = blockIdx.x * blockDim.x + threadIdx.x;
    if (idx >= E * DD) return;
    int e = idx / DD, d = idx - e * DD;
    int s = src[e], t = dst[e], r = etype[e];
    float c0 = comp[r * 2], c1 = comp[r * 2 + 1];
    float v = c0 * P0[s * DD + d] + c1 * P1[s * DD + d];
    atomicAdd(&feat[t * FEATD + d], v);
}

// ---------------- windowed 2-head attention (center query only) ----------------
__global__ void relatt_kernel(const float* __restrict__ Q, const float* __restrict__ Kb,
                              const float* __restrict__ V, float* __restrict__ ao)
{
    int l = blockIdx.x;
    int tid = threadIdx.x;
    int wrp = tid >> 5, lane = tid & 31;
    __shared__ float sc[6];
    __shared__ float alpha[6];
    if (wrp < 6) {
        int h = wrp / 3, w = wrp % 3;
        int nl = l + w - 1; nl = max(0, min(LL - 1, nl));
        float sum = 0.f;
        for (int d = h * 150 + lane; d < (h + 1) * 150; d += 32)
            sum += Q[l * DD + d] * Kb[nl * DD + d];
        for (int o = 16; o; o >>= 1) sum += __shfl_down_sync(0xffffffff, sum, o);
        if (lane == 0) sc[wrp] = sum * rsqrtf(150.f);
    }
    __syncthreads();
    if (tid < 2) {
        int h = tid;
        float m = fmaxf(sc[h * 3], fmaxf(sc[h * 3 + 1], sc[h * 3 + 2]));
        float e0 = expf(sc[h * 3] - m), e1 = expf(sc[h * 3 + 1] - m), e2 = expf(sc[h * 3 + 2] - m);
        float inv = 1.f / (e0 + e1 + e2);
        alpha[h * 3] = e0 * inv; alpha[h * 3 + 1] = e1 * inv; alpha[h * 3 + 2] = e2 * inv;
    }
    __syncthreads();
    if (tid < DD) {
        int h = tid / 150;
        float s = 0.f;
#pragma unroll
        for (int w = 0; w < 3; w++) {
            int nl = max(0, min(LL - 1, l + w - 1));
            s += alpha[h * 3 + w] * V[nl * DD + tid];
        }
        ao[l * DD + tid] = s;
    }
}

// ---------------- ||relatt_out|| per row ----------------
__global__ void rnorm_kernel(const float* __restrict__ feat, float* __restrict__ rnorm)
{
    int l = blockIdx.x; int tid = threadIdx.x;
    __shared__ float red[10];
    float v = 0.f;
    if (tid < DD) { float x = feat[l * FEATD + 300 + tid]; v = x * x; }
    for (int o = 16; o; o >>= 1) v += __shfl_down_sync(0xffffffff, v, o);
    if ((tid & 31) == 0) red[tid >> 5] = v;
    __syncthreads();
    if (tid == 0) { float s = 0.f; for (int i = 0; i < 10; i++) s += red[i]; rnorm[l] = sqrtf(s); }
}

// ---------------- concept-graph dual attention ----------------
__global__ void __launch_bounds__(512) concept_kernel(
    const int* __restrict__ src_ids, const int* __restrict__ dst_ids,
    const float* __restrict__ cw, const float* __restrict__ cs,
    const float* __restrict__ table, const float* __restrict__ rvecs,
    const float* __restrict__ feat, const float* __restrict__ rnorm,
    float* __restrict__ nodes, float* __restrict__ nscore, float* __restrict__ nmask)
{
    int s = blockIdx.x, l = blockIdx.y, g = blockIdx.z;
    int tid = threadIdx.x;
    int base3 = (g * LL + l) * SS + s;
    int base4 = base3 * KK;
    int nidx = l * NNODE + g * SS + s;
    int sid = src_ids[base3];
    if (sid < 0) {
        if (tid == 0) { nscore[nidx] = NEGV; nmask[nidx] = 0.f; }
        return;
    }
    __shared__ __align__(16) float dsh[KK][DD];
    __shared__ __align__(16) float srcsh[DD], rsh[DD], relsh[DD];
    __shared__ int ids[KK];
    __shared__ float wgt[KK], sen[KK];
    __shared__ float avals[KK], nvals[KK], bvals[KK], coef[KK];
    __shared__ float redbuf[16];

    if (tid < KK) {
        ids[tid] = dst_ids[base4 + tid];
        wgt[tid] = cw[base4 + tid];
        sen[tid] = cs[base4 + tid];
    }
    const float4* t4 = reinterpret_cast<const float4*>(table);
    const float4* r4 = reinterpret_cast<const float4*>(rvecs);
    const float4* f4 = reinterpret_cast<const float4*>(feat);
    if (tid < 75) {
        reinterpret_cast<float4*>(srcsh)[tid] = t4[sid * 75 + tid];
    } else if (tid < 150) {
        int j = tid - 75;
        reinterpret_cast<float4*>(rsh)[j] = r4[g * 75 + j];
    } else if (tid < 225) {
        int j = tid - 150;
        reinterpret_cast<float4*>(relsh)[j] = f4[(l * FEATD + 300) / 4 + j];
    }
    __syncthreads();
    for (int idx = tid; idx < KK * 75; idx += blockDim.x) {
        int k = idx / 75, j = idx - k * 75;
        int id = ids[k];
        float4 v = (id >= 0) ? t4[id * 75 + j] : make_float4(0.f, 0.f, 0.f, 0.f);
        reinterpret_cast<float4*>(&dsh[k][0])[j] = v;
    }
    __syncthreads();
    int wrp = tid >> 5, lane = tid & 31;
    {
        int k = wrp;
        float a = 0.f, n = 0.f, b = 0.f;
        for (int d = lane; d < DD; d += 32) {
            float dv = dsh[k][d];
            a += relsh[d] * dv;
            n += dv * dv;
            b += srcsh[d] * rsh[d] * dv;
        }
        for (int o = 16; o; o >>= 1) {
            a += __shfl_down_sync(0xffffffff, a, o);
            n += __shfl_down_sync(0xffffffff, n, o);
            b += __shfl_down_sync(0xffffffff, b, o);
        }
        if (lane == 0) { avals[k] = a; nvals[k] = n; bvals[k] = b; }
    }
    __syncthreads();
    if (tid == 0) {
        float rn = rnorm[l];
        float omega[KK];
        float m1 = -1e30f;
        for (int k = 0; k < KK; k++) {
            omega[k] = 0.f;
            if (ids[k] >= 0) {
                float cosv = fabsf(avals[k]) / (rn * sqrtf(nvals[k]) + 1e-8f);
                omega[k] = 0.5f * wgt[k] * cosv + 0.5f * fabsf(sen[k]);
                m1 = fmaxf(m1, omega[k]);
            }
        }
        float a1[KK]; float den = 0.f;
        for (int k = 0; k < KK; k++) { a1[k] = (ids[k] >= 0) ? expf(omega[k] - m1) : 0.f; den += a1[k]; }
        float inv = (den > 0.f) ? 1.f / den : 0.f;
        float sarr[KK]; float m2 = -1e30f;
        for (int k = 0; k < KK; k++) {
            a1[k] *= inv;
            sarr[k] = a1[k] * bvals[k];
            if (ids[k] >= 0) m2 = fmaxf(m2, sarr[k]);
        }
        float den2 = 0.f; float a2[KK];
        for (int k = 0; k < KK; k++) { a2[k] = (ids[k] >= 0) ? expf(sarr[k] - m2) : 0.f; den2 += a2[k]; }
        float inv2 = (den2 > 0.f) ? 1.f / den2 : 0.f;
        for (int k = 0; k < KK; k++) coef[k] = a1[k] * a2[k] * inv2;
    }
    __syncthreads();
    float part = 0.f;
    if (tid < DD) {
        float sum = 0.f;
#pragma unroll
        for (int k = 0; k < KK; k++) sum += coef[k] * dsh[k][tid];
        float nodeval = srcsh[tid] + rsh[tid] * sum;
        nodes[nidx * DD + tid] = nodeval;
        part = nodeval * relsh[tid];
    }
    for (int o = 16; o; o >>= 1) part += __shfl_down_sync(0xffffffff, part, o);
    if (lane == 0) redbuf[wrp] = part;
    __syncthreads();
    if (tid == 0) {
        float sc = 0.f;
        for (int i = 0; i < 16; i++) sc += redbuf[i];
        nscore[nidx] = sc; nmask[nidx] = 1.f;
    }
}

// ---------------- node softmax + sym ----------------
__global__ void sym_kernel(const float* __restrict__ nodes, const float* __restrict__ nscore,
                           const float* __restrict__ nmask, float* __restrict__ feat)
{
    int l = blockIdx.x; int tid = threadIdx.x;
    __shared__ float att[NNODE];
    __shared__ int anyv;
    if (tid == 0) {
        float m = -1e30f; int any = 0;
        for (int n = 0; n < NNODE; n++)
            if (nmask[l * NNODE + n] > 0.5f) { any = 1; m = fmaxf(m, nscore[l * NNODE + n]); }
        float den = 0.f;
        for (int n = 0; n < NNODE; n++) {
            float a = (nmask[l * NNODE + n] > 0.5f) ? expf(nscore[l * NNODE + n] - m) : 0.f;
            att[n] = a; den += a;
        }
        float inv = any ? 1.f / den : 0.f;
        for (int n = 0; n < NNODE; n++) att[n] *= inv;
        anyv = any;
    }
    __syncthreads();
    if (tid < DD) {
        float sum = 0.f;
        if (anyv) {
            for (int n = 0; n < NNODE; n++) {
                float a = att[n];
                if (a != 0.f) sum += a * nodes[(l * NNODE + n) * DD + tid];
            }
        }
        feat[l * FEATD + 600 + tid] = sum;
    }
}

// ---------------- final: sum K-chunks + bias + relu, logits, log_softmax ----------------
__global__ void final_kernel(const float* __restrict__ hp, const float* __restrict__ bfuse,
                             const float* __restrict__ Wout, const float* __restrict__ bout,
                             float* __restrict__ out)
{
    int l = blockIdx.x; int lane = threadIdx.x;  // blockDim = 32
    float hv[10];
#pragma unroll
    for (int j = 0; j < 10; j++) {
        int d = lane + 32 * j;
        float v = 0.f;
        if (d < DD) {
            v = bfuse[d] + hp[l * DD + d] + hp[76800 + l * DD + d] + hp[153600 + l * DD + d];
            v = fmaxf(v, 0.f);
        }
        hv[j] = v;
    }
    __shared__ float logits[CC];
    for (int c = 0; c < CC; c++) {
        float sum = 0.f;
#pragma unroll
        for (int j = 0; j < 10; j++) {
            int d = lane + 32 * j;
            if (d < DD) sum += hv[j] * Wout[d * CC + c];
        }
        for (int o = 16; o; o >>= 1) sum += __shfl_down_sync(0xffffffff, sum, o);
        if (lane == 0) logits[c] = sum + bout[c];
    }
    __syncwarp();
    if (lane == 0) {
        float m = -1e30f;
        for (int c = 0; c < CC; c++) m = fmaxf(m, logits[c]);
        float den = 0.f;
        for (int c = 0; c < CC; c++) den += expf(logits[c] - m);
        float lden = logf(den);
        for (int c = 0; c < CC; c++) out[l * CC + c] = logits[c] - m - lden;
    }
}

extern "C" void kernel_launch(void* const* d_in, const int* in_sizes, int n_in,
                              void* d_out, int out_size)
{
    const float* utt     = (const float*)d_in[0];
    const int*   str_src = (const int*)d_in[1];
    const int*   str_dst = (const int*)d_in[2];
    const int*   str_et  = (const int*)d_in[3];
    const int*   c_src   = (const int*)d_in[4];
    const int*   c_dst   = (const int*)d_in[5];
    const float* c_w     = (const float*)d_in[6];
    const float* c_s     = (const float*)d_in[7];
    const float* table   = (const float*)d_in[8];
    const float* W_basis = (const float*)d_in[9];
    const float* comp    = (const float*)d_in[10];
    const float* W_self  = (const float*)d_in[11];
    const float* b_rgcn  = (const float*)d_in[12];
    const float* Wq      = (const float*)d_in[13];
    const float* Wk      = (const float*)d_in[14];
    const float* Wv      = (const float*)d_in[15];
    const float* Wo      = (const float*)d_in[16];
    const float* rvecs   = (const float*)d_in[17];
    const float* W_fuse  = (const float*)d_in[18];
    const float* b_fuse  = (const float*)d_in[19];
    const float* W_out   = (const float*)d_in[20];
    const float* b_out   = (const float*)d_in[21];
    float* out = (float*)d_out;

    float* base;
    cudaGetSymbolAddress((void**)&base, g_scratch);
    float* P0     = base;
    float* P1     = base + 76800;
    float* Qb     = base + 153600;
    float* Kb     = base + 230400;
    float* Vb     = base + 307200;
    float* ao     = base + 384000;
    float* feat   = base + 460800;
    float* rn     = base + 691200;
    float* nodes  = base + 691456;
    float* nscore = base + 4377856;
    float* nmask  = base + 4390144;
    float* hpart  = base + 4402432;

    dim3 mgrid(32, 6);
    mega6_kernel<<<mgrid, 320>>>(utt, W_basis, Wq, Wk, Wv, W_self, b_rgcn,
                                 P0, P1, Qb, Kb, Vb, feat);
    edge_kernel<<<(2048 * DD + 255) / 256, 256>>>(str_src, str_dst, str_et, comp, P0, P1, feat, 2048);
    relatt_kernel<<<LL, 320>>>(Qb, Kb, Vb, ao);
    rowgemm_kernel<<<32, 320>>>(ao, Wo, feat + 300, DD, FEATD);
    rnorm_kernel<<<LL, 320>>>(feat, rn);
    dim3 cgrid(SS, LL, 3);
    concept_kernel<<<cgrid, 512>>>(c_src, c_dst, c_w, c_s, table, rvecs, feat, rn, nodes, nscore, nmask);
    sym_kernel<<<LL, 320>>>(nodes, nscore, nmask, feat);
    dim3 fgrid(32, 3);
    fuse_kernel<<<fgrid, 320>>>(feat, W_fuse, hpart);
    final_kernel<<<LL, 32>>>(hpart, b_fuse, W_out, b_out, out);
}

// round 13
// speedup vs baseline: 1.9734x; 1.0536x over previous
#include <cuda_runtime.h>
#include <math.h>

#define LL 256
#define DD 300
#define SS 16
#define KK 16
#define NNODE 48
#define CC 7
#define FEATD 900
#define NEGV -1000000000.0f
#define TKS 20    // K per step (300 = 15*20)
#define TN 64     // cols per block tile
#define XPAD 68   // padded row length for transposed X tile (17*16B)

// scratch layout (floats):
// P0:0  P1:76800  Q:153600  K:230400  V:307200  ao:384000
// feat:460800 (256*900)  rnorm:691200  nodes:691456 (256*48*300)
// nscore:4377856  nmask:4390144  hpart:4402432 (3*76800)  end:4632832
__device__ __align__(16) float g_scratch[4632832];

// ---------------- 64x64 register-blocked SGEMM core ----------------
// Block: 256 threads (tx=tid&15 -> 4-col group, ty=tid>>4 -> 4-row group).
// Computes out[r0+4ty+i][c0+4tx+j] = sum_k X[r][k]*W[k][c], K=N=300, W row stride 300.
// X must have 64 valid rows at the given pointer; cols c guarded to <300 by caller store.
__device__ __forceinline__ void sgemm_core(
    const float* __restrict__ X, int ldx, const float* __restrict__ W,
    int c0, float* xs /*[TKS*XPAD]*/, float* wt /*[TKS*TN]*/,
    int tid, float acc[4][4])
{
#pragma unroll
    for (int i = 0; i < 4; i++)
#pragma unroll
        for (int j = 0; j < 4; j++) acc[i][j] = 0.f;

    for (int k0 = 0; k0 < 300; k0 += TKS) {
        // stage X tile: 64 rows x 20 k, transposed -> xs[k][r]; 320 float4 loads
        for (int j = tid; j < 320; j += 256) {
            int r = j / 5, kq = j - r * 5;
            float4 v = *reinterpret_cast<const float4*>(X + r * ldx + k0 + 4 * kq);
            int kk = 4 * kq;
            xs[(kk + 0) * XPAD + r] = v.x;
            xs[(kk + 1) * XPAD + r] = v.y;
            xs[(kk + 2) * XPAD + r] = v.z;
            xs[(kk + 3) * XPAD + r] = v.w;
        }
        // stage W tile: 20 k x 64 cols (N-edge guarded); 320 float4
        for (int j = tid; j < 320; j += 256) {
            int kr = j / 16, cq = j - kr * 16;
            int c = c0 + 4 * cq;
            const float* wp = W + (k0 + kr) * 300 + c;
            float4 v;
            if (c + 3 < 300) {
                v = *reinterpret_cast<const float4*>(wp);
            } else {
                v.x = (c + 0 < 300) ? wp[0] : 0.f;
                v.y = (c + 1 < 300) ? wp[1] : 0.f;
                v.z = (c + 2 < 300) ? wp[2] : 0.f;
                v.w = (c + 3 < 300) ? wp[3] : 0.f;
            }
            *reinterpret_cast<float4*>(&wt[kr * TN + 4 * cq]) = v;
        }
        __syncthreads();
        int tx = tid & 15, ty = tid >> 4;
#pragma unroll
        for (int k = 0; k < TKS; k++) {
            float4 a = *reinterpret_cast<const float4*>(&xs[k * XPAD + 4 * ty]);
            float4 b = *reinterpret_cast<const float4*>(&wt[k * TN + 4 * tx]);
            acc[0][0] += a.x * b.x; acc[0][1] += a.x * b.y; acc[0][2] += a.x * b.z; acc[0][3] += a.x * b.w;
            acc[1][0] += a.y * b.x; acc[1][1] += a.y * b.y; acc[1][2] += a.y * b.z; acc[1][3] += a.y * b.w;
            acc[2][0] += a.z * b.x; acc[2][1] += a.z * b.y; acc[2][2] += a.z * b.z; acc[2][3] += a.z * b.w;
            acc[3][0] += a.w * b.x; acc[3][1] += a.w * b.y; acc[3][2] += a.w * b.z; acc[3][3] += a.w * b.w;
        }
        __syncthreads();
    }
}

// ---------------- batched 6-way utt projection ----------------
__global__ void __launch_bounds__(256) mega6_kernel(
    const float* __restrict__ utt,
    const float* __restrict__ W_basis, const float* __restrict__ Wq,
    const float* __restrict__ Wk, const float* __restrict__ Wv,
    const float* __restrict__ W_self, const float* __restrict__ b_rgcn,
    float* __restrict__ P0, float* __restrict__ P1, float* __restrict__ Qb,
    float* __restrict__ Kb, float* __restrict__ Vb, float* __restrict__ feat)
{
    __shared__ __align__(16) float xs[TKS * XPAD];
    __shared__ __align__(16) float wt[TKS * TN];
    int r0 = blockIdx.x * 64;
    int c0 = blockIdx.y * 64;
    int y = blockIdx.z;
    int tid = threadIdx.x;

    const float* W;
    float* out;
    int ldo = DD;
    int use_bias = 0;
    switch (y) {
        case 0: W = W_basis;          out = P0;   break;
        case 1: W = W_basis + 90000;  out = P1;   break;
        case 2: W = Wq;               out = Qb;   break;
        case 3: W = Wk;               out = Kb;   break;
        case 4: W = Wv;               out = Vb;   break;
        default: W = W_self;          out = feat; ldo = FEATD; use_bias = 1; break;
    }
    float acc[4][4];
    sgemm_core(utt + r0 * DD, DD, W, c0, xs, wt, tid, acc);
    int tx = tid & 15, ty = tid >> 4;
#pragma unroll
    for (int i = 0; i < 4; i++) {
        int r = r0 + 4 * ty + i;
#pragma unroll
        for (int j = 0; j < 4; j++) {
            int c = c0 + 4 * tx + j;
            if (c < DD) out[r * ldo + c] = acc[i][j] + (use_bias ? b_rgcn[c] : 0.f);
        }
    }
}

// ---------------- Wo matvec ----------------
__global__ void __launch_bounds__(256) rowgemm_kernel(
    const float* __restrict__ X, const float* __restrict__ W,
    float* __restrict__ out, int ldx, int ldo)
{
    __shared__ __align__(16) float xs[TKS * XPAD];
    __shared__ __align__(16) float wt[TKS * TN];
    int r0 = blockIdx.x * 64;
    int c0 = blockIdx.y * 64;
    int tid = threadIdx.x;
    float acc[4][4];
    sgemm_core(X + r0 * ldx, ldx, W, c0, xs, wt, tid, acc);
    int tx = tid & 15, ty = tid >> 4;
#pragma unroll
    for (int i = 0; i < 4; i++) {
        int r = r0 + 4 * ty + i;
#pragma unroll
        for (int j = 0; j < 4; j++) {
            int c = c0 + 4 * tx + j;
            if (c < DD) out[r * ldo + c] = acc[i][j];
        }
    }
}

// ---------------- fuse GEMM, K split in 3 chunks ----------------
__global__ void __launch_bounds__(256) fuse_kernel(
    const float* __restrict__ feat, const float* __restrict__ Wfuse,
    float* __restrict__ hpart)
{
    __shared__ __align__(16) float xs[TKS * XPAD];
    __shared__ __align__(16) float wt[TKS * TN];
    int r0 = blockIdx.x * 64;
    int c0 = blockIdx.y * 64;
    int ch = blockIdx.z;
    int tid = threadIdx.x;
    float acc[4][4];
    sgemm_core(feat + r0 * FEATD + ch * DD, FEATD, Wfuse + ch * 90000, c0, xs, wt, tid, acc);
    int tx = tid & 15, ty = tid >> 4;
#pragma unroll
    for (int i = 0; i < 4; i++) {
        int r = r0 + 4 * ty + i;
#pragma unroll
        for (int j = 0; j < 4; j++) {
            int c = c0 + 4 * tx + j;
            if (c < DD) hpart[ch * 76800 + r * DD + c] = acc[i][j];
        }
    }
}

// ---------------- RGCN edge scatter ----------------
__global__ void edge_kernel(const int* __restrict__ src, const int* __restrict__ dst,
                            const int* __restrict__ etype, const float* __restrict__ comp,
                            const float* __restrict__ P0, const float* __restrict__ P1,
                            float* __restrict__ feat, int E)
{
    int idx = blockIdx.x * blockDim.x + threadIdx.x;
    if (idx >= E * DD) return;
    int e = idx / DD, d = idx - e * DD;
    int s = src[e], t = dst[e], r = etype[e];
    float c0 = comp[r * 2], c1 = comp[r * 2 + 1];
    float v = c0 * P0[s * DD + d] + c1 * P1[s * DD + d];
    atomicAdd(&feat[t * FEATD + d], v);
}

// ---------------- windowed 2-head attention (center query only) ----------------
__global__ void relatt_kernel(const float* __restrict__ Q, const float* __restrict__ Kb,
                              const float* __restrict__ V, float* __restrict__ ao)
{
    int l = blockIdx.x;
    int tid = threadIdx.x;
    int wrp = tid >> 5, lane = tid & 31;
    __shared__ float sc[6];
    __shared__ float alpha[6];
    if (wrp < 6) {
        int h = wrp / 3, w = wrp % 3;
        int nl = l + w - 1; nl = max(0, min(LL - 1, nl));
        float sum = 0.f;
        for (int d = h * 150 + lane; d < (h + 1) * 150; d += 32)
            sum += Q[l * DD + d] * Kb[nl * DD + d];
        for (int o = 16; o; o >>= 1) sum += __shfl_down_sync(0xffffffff, sum, o);
        if (lane == 0) sc[wrp] = sum * rsqrtf(150.f);
    }
    __syncthreads();
    if (tid < 2) {
        int h = tid;
        float m = fmaxf(sc[h * 3], fmaxf(sc[h * 3 + 1], sc[h * 3 + 2]));
        float e0 = expf(sc[h * 3] - m), e1 = expf(sc[h * 3 + 1] - m), e2 = expf(sc[h * 3 + 2] - m);
        float inv = 1.f / (e0 + e1 + e2);
        alpha[h * 3] = e0 * inv; alpha[h * 3 + 1] = e1 * inv; alpha[h * 3 + 2] = e2 * inv;
    }
    __syncthreads();
    if (tid < DD) {
        int h = tid / 150;
        float s = 0.f;
#pragma unroll
        for (int w = 0; w < 3; w++) {
            int nl = max(0, min(LL - 1, l + w - 1));
            s += alpha[h * 3 + w] * V[nl * DD + tid];
        }
        ao[l * DD + tid] = s;
    }
}

// ---------------- ||relatt_out|| per row ----------------
__global__ void rnorm_kernel(const float* __restrict__ feat, float* __restrict__ rnorm)
{
    int l = blockIdx.x; int tid = threadIdx.x;
    __shared__ float red[10];
    float v = 0.f;
    if (tid < DD) { float x = feat[l * FEATD + 300 + tid]; v = x * x; }
    for (int o = 16; o; o >>= 1) v += __shfl_down_sync(0xffffffff, v, o);
    if ((tid & 31) == 0) red[tid >> 5] = v;
    __syncthreads();
    if (tid == 0) { float s = 0.f; for (int i = 0; i < 10; i++) s += red[i]; rnorm[l] = sqrtf(s); }
}

// ---------------- concept-graph dual attention ----------------
__global__ void __launch_bounds__(512) concept_kernel(
    const int* __restrict__ src_ids, const int* __restrict__ dst_ids,
    const float* __restrict__ cw, const float* __restrict__ cs,
    const float* __restrict__ table, const float* __restrict__ rvecs,
    const float* __restrict__ feat, const float* __restrict__ rnorm,
    float* __restrict__ nodes, float* __restrict__ nscore, float* __restrict__ nmask)
{
    int s = blockIdx.x, l = blockIdx.y, g = blockIdx.z;
    int tid = threadIdx.x;
    int base3 = (g * LL + l) * SS + s;
    int base4 = base3 * KK;
    int nidx = l * NNODE + g * SS + s;
    int sid = src_ids[base3];
    if (sid < 0) {
        if (tid == 0) { nscore[nidx] = NEGV; nmask[nidx] = 0.f; }
        return;
    }
    __shared__ __align__(16) float dsh[KK][DD];
    __shared__ __align__(16) float srcsh[DD], rsh[DD], relsh[DD];
    __shared__ int ids[KK];
    __shared__ float wgt[KK], sen[KK];
    __shared__ float avals[KK], nvals[KK], bvals[KK], coef[KK];
    __shared__ float redbuf[16];

    if (tid < KK) {
        ids[tid] = dst_ids[base4 + tid];
        wgt[tid] = cw[base4 + tid];
        sen[tid] = cs[base4 + tid];
    }
    const float4* t4 = reinterpret_cast<const float4*>(table);
    const float4* r4 = reinterpret_cast<const float4*>(rvecs);
    const float4* f4 = reinterpret_cast<const float4*>(feat);
    if (tid < 75) {
        reinterpret_cast<float4*>(srcsh)[tid] = t4[sid * 75 + tid];
    } else if (tid < 150) {
        int j = tid - 75;
        reinterpret_cast<float4*>(rsh)[j] = r4[g * 75 + j];
    } else if (tid < 225) {
        int j = tid - 150;
        reinterpret_cast<float4*>(relsh)[j] = f4[(l * FEATD + 300) / 4 + j];
    }
    __syncthreads();
    for (int idx = tid; idx < KK * 75; idx += blockDim.x) {
        int k = idx / 75, j = idx - k * 75;
        int id = ids[k];
        float4 v = (id >= 0) ? t4[id * 75 + j] : make_float4(0.f, 0.f, 0.f, 0.f);
        reinterpret_cast<float4*>(&dsh[k][0])[j] = v;
    }
    __syncthreads();
    int wrp = tid >> 5, lane = tid & 31;
    {
        int k = wrp;
        float a = 0.f, n = 0.f, b = 0.f;
        for (int d = lane; d < DD; d += 32) {
            float dv = dsh[k][d];
            a += relsh[d] * dv;
            n += dv * dv;
            b += srcsh[d] * rsh[d] * dv;
        }
        for (int o = 16; o; o >>= 1) {
            a += __shfl_down_sync(0xffffffff, a, o);
            n += __shfl_down_sync(0xffffffff, n, o);
            b += __shfl_down_sync(0xffffffff, b, o);
        }
        if (lane == 0) { avals[k] = a; nvals[k] = n; bvals[k] = b; }
    }
    __syncthreads();
    if (tid == 0) {
        float rn = rnorm[l];
        float omega[KK];
        float m1 = -1e30f;
        for (int k = 0; k < KK; k++) {
            omega[k] = 0.f;
            if (ids[k] >= 0) {
                float cosv = fabsf(avals[k]) / (rn * sqrtf(nvals[k]) + 1e-8f);
                omega[k] = 0.5f * wgt[k] * cosv + 0.5f * fabsf(sen[k]);
                m1 = fmaxf(m1, omega[k]);
            }
        }
        float a1[KK]; float den = 0.f;
        for (int k = 0; k < KK; k++) { a1[k] = (ids[k] >= 0) ? expf(omega[k] - m1) : 0.f; den += a1[k]; }
        float inv = (den > 0.f) ? 1.f / den : 0.f;
        float sarr[KK]; float m2 = -1e30f;
        for (int k = 0; k < KK; k++) {
            a1[k] *= inv;
            sarr[k] = a1[k] * bvals[k];
            if (ids[k] >= 0) m2 = fmaxf(m2, sarr[k]);
        }
        float den2 = 0.f; float a2[KK];
        for (int k = 0; k < KK; k++) { a2[k] = (ids[k] >= 0) ? expf(sarr[k] - m2) : 0.f; den2 += a2[k]; }
        float inv2 = (den2 > 0.f) ? 1.f / den2 : 0.f;
        for (int k = 0; k < KK; k++) coef[k] = a1[k] * a2[k] * inv2;
    }
    __syncthreads();
    float part = 0.f;
    if (tid < DD) {
        float sum = 0.f;
#pragma unroll
        for (int k = 0; k < KK; k++) sum += coef[k] * dsh[k][tid];
        float nodeval = srcsh[tid] + rsh[tid] * sum;
        nodes[nidx * DD + tid] = nodeval;
        part = nodeval * relsh[tid];
    }
    for (int o = 16; o; o >>= 1) part += __shfl_down_sync(0xffffffff, part, o);
    if (lane == 0) redbuf[wrp] = part;
    __syncthreads();
    if (tid == 0) {
        float sc = 0.f;
        for (int i = 0; i < 16; i++) sc += redbuf[i];
        nscore[nidx] = sc; nmask[nidx] = 1.f;
    }
}

// ---------------- node softmax + sym ----------------
__global__ void sym_kernel(const float* __restrict__ nodes, const float* __restrict__ nscore,
                           const float* __restrict__ nmask, float* __restrict__ feat)
{
    int l = blockIdx.x; int tid = threadIdx.x;
    __shared__ float att[NNODE];
    __shared__ int anyv;
    if (tid == 0) {
        float m = -1e30f; int any = 0;
        for (int n = 0; n < NNODE; n++)
            if (nmask[l * NNODE + n] > 0.5f) { any = 1; m = fmaxf(m, nscore[l * NNODE + n]); }
        float den = 0.f;
        for (int n = 0; n < NNODE; n++) {
            float a = (nmask[l * NNODE + n] > 0.5f) ? expf(nscore[l * NNODE + n] - m) : 0.f;
            att[n] = a; den += a;
        }
        float inv = any ? 1.f / den : 0.f;
        for (int n = 0; n < NNODE; n++) att[n] *= inv;
        anyv = any;
    }
    __syncthreads();
    if (tid < DD) {
        float sum = 0.f;
        if (anyv) {
            for (int n = 0; n < NNODE; n++) {
                float a = att[n];
                if (a != 0.f) sum += a * nodes[(l * NNODE + n) * DD + tid];
            }
        }
        feat[l * FEATD + 600 + tid] = sum;
    }
}

// ---------------- final: sum K-chunks + bias + relu, logits, log_softmax ----------------
__global__ void final_kernel(const float* __restrict__ hp, const float* __restrict__ bfuse,
                             const float* __restrict__ Wout, const float* __restrict__ bout,
                             float* __restrict__ out)
{
    int l = blockIdx.x; int lane = threadIdx.x;  // blockDim = 32
    float hv[10];
#pragma unroll
    for (int j = 0; j < 10; j++) {
        int d = lane + 32 * j;
        float v = 0.f;
        if (d < DD) {
            v = bfuse[d] + hp[l * DD + d] + hp[76800 + l * DD + d] + hp[153600 + l * DD + d];
            v = fmaxf(v, 0.f);
        }
        hv[j] = v;
    }
    __shared__ float logits[CC];
    for (int c = 0; c < CC; c++) {
        float sum = 0.f;
#pragma unroll
        for (int j = 0; j < 10; j++) {
            int d = lane + 32 * j;
            if (d < DD) sum += hv[j] * Wout[d * CC + c];
        }
        for (int o = 16; o; o >>= 1) sum += __shfl_down_sync(0xffffffff, sum, o);
        if (lane == 0) logits[c] = sum + bout[c];
    }
    __syncwarp();
    if (lane == 0) {
        float m = -1e30f;
        for (int c = 0; c < CC; c++) m = fmaxf(m, logits[c]);
        float den = 0.f;
        for (int c = 0; c < CC; c++) den += expf(logits[c] - m);
        float lden = logf(den);
        for (int c = 0; c < CC; c++) out[l * CC + c] = logits[c] - m - lden;
    }
}

extern "C" void kernel_launch(void* const* d_in, const int* in_sizes, int n_in,
                              void* d_out, int out_size)
{
    const float* utt     = (const float*)d_in[0];
    const int*   str_src = (const int*)d_in[1];
    const int*   str_dst = (const int*)d_in[2];
    const int*   str_et  = (const int*)d_in[3];
    const int*   c_src   = (const int*)d_in[4];
    const int*   c_dst   = (const int*)d_in[5];
    const float* c_w     = (const float*)d_in[6];
    const float* c_s     = (const float*)d_in[7];
    const float* table   = (const float*)d_in[8];
    const float* W_basis = (const float*)d_in[9];
    const float* comp    = (const float*)d_in[10];
    const float* W_self  = (const float*)d_in[11];
    const float* b_rgcn  = (const float*)d_in[12];
    const float* Wq      = (const float*)d_in[13];
    const float* Wk      = (const float*)d_in[14];
    const float* Wv      = (const float*)d_in[15];
    const float* Wo      = (const float*)d_in[16];
    const float* rvecs   = (const float*)d_in[17];
    const float* W_fuse  = (const float*)d_in[18];
    const float* b_fuse  = (const float*)d_in[19];
    const float* W_out   = (const float*)d_in[20];
    const float* b_out   = (const float*)d_in[21];
    float* out = (float*)d_out;

    float* base;
    cudaGetSymbolAddress((void**)&base, g_scratch);
    float* P0     = base;
    float* P1     = base + 76800;
    float* Qb     = base + 153600;
    float* Kb     = base + 230400;
    float* Vb     = base + 307200;
    float* ao     = base + 384000;
    float* feat   = base + 460800;
    float* rn     = base + 691200;
    float* nodes  = base + 691456;
    float* nscore = base + 4377856;
    float* nmask  = base + 4390144;
    float* hpart  = base + 4402432;

    dim3 mgrid(4, 5, 6);
    mega6_kernel<<<mgrid, 256>>>(utt, W_basis, Wq, Wk, Wv, W_self, b_rgcn,
                                 P0, P1, Qb, Kb, Vb, feat);
    edge_kernel<<<(2048 * DD + 255) / 256, 256>>>(str_src, str_dst, str_et, comp, P0, P1, feat, 2048);
    relatt_kernel<<<LL, 320>>>(Qb, Kb, Vb, ao);
    dim3 wgrid(4, 5);
    rowgemm_kernel<<<wgrid, 256>>>(ao, Wo, feat + 300, DD, FEATD);
    rnorm_kernel<<<LL, 320>>>(feat, rn);
    dim3 cgrid(SS, LL, 3);
    concept_kernel<<<cgrid, 512>>>(c_src, c_dst, c_w, c_s, table, rvecs, feat, rn, nodes, nscore, nmask);
    sym_kernel<<<LL, 320>>>(nodes, nscore, nmask, feat);
    dim3 fgrid(4, 5, 3);
    fuse_kernel<<<fgrid, 256>>>(feat, W_fuse, hpart);
    final_kernel<<<LL, 32>>>(hpart, b_fuse, W_out, b_out, out);
}